// round 8
// baseline (speedup 1.0000x reference)
#include <cuda_runtime.h>
#include <cuda_fp16.h>
#include <cstdint>
#include <cstddef>

#define IN 2048
#define DIM 128
#define NBATCH 4
#define ITERS 50
#define KELEMS (NBATCH*IN*IN)   // 16,777,216 elements

#define SKT 384                  // sinkhorn threads per block (12 warps)
#define NW  12                   // warps per sinkhorn block

// dynamic smem: v (4KB) + per-warp column partials (12 x 2048 halves = 48KB)
#define SMEM_V_BYTES 4096
#define SMEM_TOTAL_BYTES (SMEM_V_BYTES + NW * IN * 2)

// ---------------- scratch (static device globals: allocation-free) ----------
__device__ __half g_K1[KELEMS];                // K for OT1 (src,tgt)  33.5 MB
__device__ __half g_K2[KELEMS];                // K for OT2 (tgt,gen)  33.5 MB
__device__ float g_A[2][3][NBATCH*IN];         // triple-buffered column accumulators
__device__ float g_u[2][NBATCH*IN];            // final u per OT
__device__ float g_vfin[2][NBATCH*IN];         // final v per OT
__device__ unsigned g_bar8[8 * 32];            // per-(segment,OT) barrier counters

// exp(1 - c) for c in [-1,1]; degree-9 Taylor of exp(t), t=-c, times e.
__device__ __forceinline__ float exp_shift(float c){
    float t = -c;
    float p = 2.7557319e-6f;
    p = fmaf(p, t, 2.4801587e-5f);
    p = fmaf(p, t, 1.9841270e-4f);
    p = fmaf(p, t, 1.3888889e-3f);
    p = fmaf(p, t, 8.3333333e-3f);
    p = fmaf(p, t, 4.1666667e-2f);
    p = fmaf(p, t, 1.6666667e-1f);
    p = fmaf(p, t, 0.5f);
    p = fmaf(p, t, 1.0f);
    p = fmaf(p, t, 1.0f);
    return 2.7182818284f * p;
}

// ---------------- init ------------------------------------------------------
__global__ void init_kernel(float* out){
    int idx = blockIdx.x * blockDim.x + threadIdx.x;
    if (idx == 0) out[0] = 0.0f;
    if (idx < 8 * 32) g_bar8[idx] = 0u;
    if (idx < NBATCH*IN){
        g_A[0][0][idx] = 1.0f;   // epoch 0 reads buf0 => v = ones
        g_A[1][0][idx] = 1.0f;
        g_A[0][1][idx] = 0.0f;   // epoch 0 accumulates into buf1
        g_A[1][1][idx] = 0.0f;
        g_A[0][2][idx] = 0.0f;
        g_A[1][2][idx] = 0.0f;
    }
}

// ---------------- tensor-core GEMM + exp -> fp16 K --------------------------
#define SA 72   // smem row stride in halves

__global__ __launch_bounds__(256) void gemm_exp_hmma(
        const float* __restrict__ src, const float* __restrict__ tgt,
        const float* __restrict__ gen){
    int ot = blockIdx.z >> 2;
    int b  = blockIdx.z & 3;
    const float* q  = (ot ? tgt : src) + (size_t)b * IN * DIM;
    const float* kk = (ot ? gen : tgt) + (size_t)b * IN * DIM;
    __half* Kout    = (ot ? g_K2 : g_K1) + (size_t)b * IN * IN;
    int i0 = blockIdx.y * 128;
    int o0 = blockIdx.x * 128;

    __shared__ __half As[128 * SA];
    __shared__ __half Bs[128 * SA];

    int tid  = threadIdx.x;
    int lane = tid & 31, warp = tid >> 5;
    int wr = warp >> 2, wc = warp & 3;

    float c[4][4][4];
    #pragma unroll
    for (int mi = 0; mi < 4; mi++)
        #pragma unroll
        for (int ni = 0; ni < 4; ni++)
            #pragma unroll
            for (int j = 0; j < 4; j++) c[mi][ni][j] = 0.f;

    for (int dc = 0; dc < DIM; dc += 64){
        #pragma unroll
        for (int l = 0; l < 8; l++){
            int fidx = tid + 256 * l;       // 0..2047
            int r  = fidx >> 4;
            int f4 = (fidx & 15) << 2;
            float4 va = *(const float4*)(q  + (size_t)(i0 + r) * DIM + dc + f4);
            float4 vb = *(const float4*)(kk + (size_t)(o0 + r) * DIM + dc + f4);
            __half2 a0 = __floats2half2_rn(va.x, va.y);
            __half2 a1 = __floats2half2_rn(va.z, va.w);
            __half2 b0 = __floats2half2_rn(vb.x, vb.y);
            __half2 b1 = __floats2half2_rn(vb.z, vb.w);
            uint2 pa = make_uint2(*(uint32_t*)&a0, *(uint32_t*)&a1);
            uint2 pb = make_uint2(*(uint32_t*)&b0, *(uint32_t*)&b1);
            *(uint2*)&As[r * SA + f4] = pa;
            *(uint2*)&Bs[r * SA + f4] = pb;
        }
        __syncthreads();

        #pragma unroll
        for (int ks = 0; ks < 4; ks++){
            int k0 = ks * 16;
            uint32_t af[4][4], bf[4][2];
            #pragma unroll
            for (int mi = 0; mi < 4; mi++){
                int row = wr * 64 + mi * 16 + (lane & 7) + ((lane >> 3) & 1) * 8;
                int col = k0 + (lane >> 4) * 8;
                uint32_t ad = (uint32_t)__cvta_generic_to_shared(&As[row * SA + col]);
                asm volatile("ldmatrix.sync.aligned.m8n8.x4.shared.b16 {%0,%1,%2,%3}, [%4];"
                    : "=r"(af[mi][0]), "=r"(af[mi][1]), "=r"(af[mi][2]), "=r"(af[mi][3])
                    : "r"(ad));
            }
            #pragma unroll
            for (int ni = 0; ni < 4; ni++){
                int rowb = wc * 32 + ni * 8 + (lane & 7);
                int colb = k0 + ((lane >> 3) & 1) * 8;
                uint32_t ad = (uint32_t)__cvta_generic_to_shared(&Bs[rowb * SA + colb]);
                asm volatile("ldmatrix.sync.aligned.m8n8.x2.shared.b16 {%0,%1}, [%2];"
                    : "=r"(bf[ni][0]), "=r"(bf[ni][1])
                    : "r"(ad));
            }
            #pragma unroll
            for (int mi = 0; mi < 4; mi++)
                #pragma unroll
                for (int ni = 0; ni < 4; ni++){
                    asm volatile(
                        "mma.sync.aligned.m16n8k16.row.col.f32.f16.f16.f32 "
                        "{%0,%1,%2,%3}, {%4,%5,%6,%7}, {%8,%9}, {%0,%1,%2,%3};"
                        : "+f"(c[mi][ni][0]), "+f"(c[mi][ni][1]),
                          "+f"(c[mi][ni][2]), "+f"(c[mi][ni][3])
                        : "r"(af[mi][0]), "r"(af[mi][1]), "r"(af[mi][2]), "r"(af[mi][3]),
                          "r"(bf[ni][0]), "r"(bf[ni][1]));
                }
        }
        __syncthreads();
    }

    // epilogue: exp(1-c), diag = e^-10, write half2 pairs directly
    int rbase = i0 + wr * 64 + (lane >> 2);
    int cbase = o0 + wc * 32 + (lane & 3) * 2;
    #pragma unroll
    for (int mi = 0; mi < 4; mi++){
        #pragma unroll
        for (int ni = 0; ni < 4; ni++){
            int ce = cbase + ni * 8;
            #pragma unroll
            for (int h = 0; h < 2; h++){
                int re = rbase + mi * 16 + h * 8;
                float fx = (re == ce    ) ? 4.5399930e-5f : exp_shift(c[mi][ni][h*2+0]);
                float fy = (re == ce + 1) ? 4.5399930e-5f : exp_shift(c[mi][ni][h*2+1]);
                *(__half2*)(Kout + (size_t)re * IN + ce) = __floats2half2_rn(fx, fy);
            }
        }
    }
}

// ---------------- persistent fused Sinkhorn (pipelined single pass) ---------
// 384 threads (12 warps) => 170-reg budget enabling a double-buffered row
// pipeline: next row's 8 LDGs issue before the current row's reduce, hiding
// L2 latency. Each K row read ONCE per epoch: dot -> u -> acc += u*K.
__global__ __launch_bounds__(SKT, 1) void sinkhorn_kernel(int nblocks){
    extern __shared__ __align__(16) char dynsm[];
    __half2* v_sh = (__half2*)dynsm;                     // 4 KB
    __half*  part = (__half*)(dynsm + SMEM_V_BYTES);     // [NW][2048] halves

    int tid  = threadIdx.x;
    int lane = tid & 31, warp = tid >> 5;

    int seg = blockIdx.x & 3;                       // batch segment 0..3
    int bis = blockIdx.x >> 2;
    int nbs = (nblocks - seg + 3) >> 2;             // blocks in this segment
    int r0 = (int)(((long)IN * bis) / nbs);
    int r1 = (int)(((long)IN * (bis + 1)) / nbs);

    for (int e = 0; e < ITERS; e++){
        for (int ot = 0; ot < 2; ot++){
            unsigned* mybar = &g_bar8[(seg * 2 + ot) * 32];
            // wait for ALL blocks to have flushed epoch e-1 of this OT
            if (e > 0){
                if (tid == 0){
                    volatile unsigned* vb = mybar;
                    unsigned target = (unsigned)e * (unsigned)nbs;
                    while (*vb < target) { __nanosleep(32); }
                }
                __syncthreads();
            }
            const __half* Kb = (ot ? g_K2 : g_K1) + (size_t)seg * IN * IN;
            const float* Ar = &g_A[ot][e % 3][seg * IN];
            float*       Az = &g_A[ot][(e + 2) % 3][seg * IN];
            for (int o = tid; o < IN; o += SKT){
                float v = 1.0f / __ldcg(Ar + o);
                ((__half*)v_sh)[o] = __float2half_rn(v);
                Az[o] = 0.0f;                        // idempotent zero for next epoch
            }
            __syncthreads();

            // ---- pipelined fused pass ----
            __half2 acc[32];
            #pragma unroll
            for (int j = 0; j < 32; j++) acc[j] = __float2half2_rn(0.f);
            {
                const uint4* V4 = (const uint4*)v_sh;
                int row = r0 + warp;
                if (row < r1){
                    uint4 kc[8];
                    {
                        const uint4* Kr = (const uint4*)(Kb + (size_t)row * IN);
                        #pragma unroll
                        for (int j = 0; j < 8; j++) kc[j] = Kr[j * 32 + lane];
                    }
                    while (row < r1){
                        int rown = row + NW;
                        // prefetch next row (clamped: redundant-but-safe on last iter)
                        const uint4* Kn = (const uint4*)(Kb +
                            (size_t)(rown < r1 ? rown : row) * IN);
                        uint4 kn[8];
                        #pragma unroll
                        for (int j = 0; j < 8; j++) kn[j] = Kn[j * 32 + lane];
                        // dot of current row with v
                        float ax = 0.f, ay = 0.f;
                        #pragma unroll
                        for (int j = 0; j < 8; j++){
                            uint4 vv = V4[j * 32 + lane];
                            __half2 s = __hadd2(
                                __hadd2(__hmul2(*(__half2*)&kc[j].x, *(__half2*)&vv.x),
                                        __hmul2(*(__half2*)&kc[j].y, *(__half2*)&vv.y)),
                                __hadd2(__hmul2(*(__half2*)&kc[j].z, *(__half2*)&vv.z),
                                        __hmul2(*(__half2*)&kc[j].w, *(__half2*)&vv.w)));
                            float2 f = __half22float2(s);
                            ax += f.x; ay += f.y;
                        }
                        float dot = ax + ay;
                        #pragma unroll
                        for (int off = 16; off; off >>= 1)
                            dot += __shfl_xor_sync(0xffffffffu, dot, off);
                        float u = 1.0f / dot;            // all lanes have it
                        if (lane == 0) g_u[ot][seg * IN + row] = u;
                        __half2 u2 = __float2half2_rn(u);
                        #pragma unroll
                        for (int j = 0; j < 8; j++){
                            acc[j*4+0] = __hfma2(u2, *(__half2*)&kc[j].x, acc[j*4+0]);
                            acc[j*4+1] = __hfma2(u2, *(__half2*)&kc[j].y, acc[j*4+1]);
                            acc[j*4+2] = __hfma2(u2, *(__half2*)&kc[j].z, acc[j*4+2]);
                            acc[j*4+3] = __hfma2(u2, *(__half2*)&kc[j].w, acc[j*4+3]);
                        }
                        #pragma unroll
                        for (int j = 0; j < 8; j++) kc[j] = kn[j];
                        row = rown;
                    }
                }
            }
            // ---- write per-warp column partials to smem ----
            #pragma unroll
            for (int j = 0; j < 8; j++){
                uint4 o;
                o.x = *(uint32_t*)&acc[j*4+0];
                o.y = *(uint32_t*)&acc[j*4+1];
                o.z = *(uint32_t*)&acc[j*4+2];
                o.w = *(uint32_t*)&acc[j*4+3];
                *(uint4*)&part[warp * IN + j * 256 + lane * 8] = o;
            }
            __syncthreads();

            // ---- cross-warp tree sum + global flush (4 cols per thread) ----
            {
                float* Aw = &g_A[ot][(e + 1) % 3][seg * IN];
                for (int base = 0; base < IN; base += SKT * 4){
                    int c = base + tid * 4;
                    if (c < IN){
                        float s0 = 0.f, s1 = 0.f, s2 = 0.f, s3 = 0.f;
                        #pragma unroll
                        for (int w = 0; w < NW; w++){
                            uint2 hv = *(const uint2*)&part[w * IN + c];
                            float2 f0 = __half22float2(*(__half2*)&hv.x);
                            float2 f1 = __half22float2(*(__half2*)&hv.y);
                            s0 += f0.x; s1 += f0.y; s2 += f1.x; s3 += f1.y;
                        }
                        atomicAdd(Aw + c + 0, s0);
                        atomicAdd(Aw + c + 1, s1);
                        atomicAdd(Aw + c + 2, s2);
                        atomicAdd(Aw + c + 3, s3);
                    }
                }
            }

            // arrive (no wait): wait happens at top of next epoch for this OT
            __threadfence();
            __syncthreads();
            if (tid == 0) atomicAdd(mybar, 1u);
        }
    }

    // wait for both OT barriers to fully drain, then fused vfin
    if (tid == 0){
        volatile unsigned* v1 = &g_bar8[(seg * 2 + 0) * 32];
        volatile unsigned* v2 = &g_bar8[(seg * 2 + 1) * 32];
        unsigned target = (unsigned)ITERS * (unsigned)nbs;
        while (*v1 < target) { __nanosleep(32); }
        while (*v2 < target) { __nanosleep(32); }
    }
    __syncthreads();
    // final A for epoch 49 lives in buf (49+1)%3 == 2
    for (int idx = bis * SKT + tid; idx < 2 * IN; idx += nbs * SKT){
        int o = idx >> 11;
        int r = seg * IN + (idx & 2047);
        g_vfin[o][r] = 1.0f / __ldcg(&g_A[o][2][r]);
    }
}

// ---------------- loss: mean |u1 K1 v1 - u2 K2 v2| --------------------------
__global__ __launch_bounds__(256) void loss_kernel(float* __restrict__ out){
    const uint4* K1 = (const uint4*)g_K1;
    const uint4* K2 = (const uint4*)g_K2;
    const float4* V1 = (const float4*)g_vfin[0];
    const float4* V2 = (const float4*)g_vfin[1];
    int total = KELEMS / 8;
    float s = 0.f;
    for (int idx = blockIdx.x * blockDim.x + threadIdx.x; idx < total;
         idx += gridDim.x * blockDim.x){
        int o8 = idx & 255;          // uint4 (8 halves) within row
        int t  = idx >> 8;
        int i  = t & 2047;
        int b  = t >> 11;
        int row = b * IN + i;
        float u1 = g_u[0][row], u2 = g_u[1][row];
        uint4 k1 = K1[idx], k2 = K2[idx];
        float4 v1a = V1[b * 512 + o8 * 2], v1b = V1[b * 512 + o8 * 2 + 1];
        float4 v2a = V2[b * 512 + o8 * 2], v2b = V2[b * 512 + o8 * 2 + 1];
        float2 a0 = __half22float2(*(__half2*)&k1.x);
        float2 a1 = __half22float2(*(__half2*)&k1.y);
        float2 a2 = __half22float2(*(__half2*)&k1.z);
        float2 a3 = __half22float2(*(__half2*)&k1.w);
        float2 b0 = __half22float2(*(__half2*)&k2.x);
        float2 b1 = __half22float2(*(__half2*)&k2.y);
        float2 b2 = __half22float2(*(__half2*)&k2.z);
        float2 b3 = __half22float2(*(__half2*)&k2.w);
        s += fabsf(u1 * a0.x * v1a.x - u2 * b0.x * v2a.x);
        s += fabsf(u1 * a0.y * v1a.y - u2 * b0.y * v2a.y);
        s += fabsf(u1 * a1.x * v1a.z - u2 * b1.x * v2a.z);
        s += fabsf(u1 * a1.y * v1a.w - u2 * b1.y * v2a.w);
        s += fabsf(u1 * a2.x * v1b.x - u2 * b2.x * v2b.x);
        s += fabsf(u1 * a2.y * v1b.y - u2 * b2.y * v2b.y);
        s += fabsf(u1 * a3.x * v1b.z - u2 * b3.x * v2b.z);
        s += fabsf(u1 * a3.y * v1b.w - u2 * b3.y * v2b.w);
    }
    __shared__ float red[256];
    red[threadIdx.x] = s;
    __syncthreads();
    for (int st = 128; st; st >>= 1){
        if (threadIdx.x < st) red[threadIdx.x] += red[threadIdx.x + st];
        __syncthreads();
    }
    if (threadIdx.x == 0) atomicAdd(out, red[0] * (1.0f / 16777216.0f));
}

// ---------------- launch ----------------------------------------------------
extern "C" void kernel_launch(void* const* d_in, const int* in_sizes, int n_in,
                              void* d_out, int out_size){
    const float* src = (const float*)d_in[0];
    const float* tgt = (const float*)d_in[1];
    const float* gen = (const float*)d_in[2];
    float* out = (float*)d_out;

    int dev = 0;
    cudaGetDevice(&dev);
    int sm = 148;
    cudaDeviceGetAttribute(&sm, cudaDevAttrMultiProcessorCount, dev);

    cudaFuncSetAttribute(sinkhorn_kernel,
                         cudaFuncAttributeMaxDynamicSharedMemorySize,
                         SMEM_TOTAL_BYTES);

    init_kernel<<<32, 256>>>(out);
    dim3 ggrid(IN / 128, IN / 128, 8);
    gemm_exp_hmma<<<ggrid, 256>>>(src, tgt, gen);
    sinkhorn_kernel<<<sm, SKT, SMEM_TOTAL_BYTES>>>(sm);
    loss_kernel<<<2048, 256>>>(out);
}

// round 9
// speedup vs baseline: 1.0486x; 1.0486x over previous
#include <cuda_runtime.h>
#include <cuda_fp16.h>
#include <cstdint>
#include <cstddef>

#define IN 2048
#define DIM 128
#define NBATCH 4
#define ITERS 50
#define KELEMS (NBATCH*IN*IN)   // 16,777,216 elements

// dynamic smem: v (4KB) + per-warp column partials (16 x 2048 halves = 64KB)
#define SMEM_V_BYTES 4096
#define SMEM_TOTAL_BYTES (SMEM_V_BYTES + 16 * IN * 2)

// ---------------- scratch (static device globals: allocation-free) ----------
__device__ __half g_K1[KELEMS];                // K for OT1 (src,tgt)  33.5 MB
__device__ __half g_K2[KELEMS];                // K for OT2 (tgt,gen)  33.5 MB
__device__ float g_A[2][3][NBATCH*IN];         // triple-buffered column accumulators
__device__ float g_u[2][NBATCH*IN];            // final u per OT
__device__ float g_vfin[2][NBATCH*IN];         // final v per OT
__device__ unsigned g_bar8[8 * 32];            // per-(segment,OT) barrier counters

// exp(1 - c) for c in [-1,1]; degree-9 Taylor of exp(t), t=-c, times e.
__device__ __forceinline__ float exp_shift(float c){
    float t = -c;
    float p = 2.7557319e-6f;
    p = fmaf(p, t, 2.4801587e-5f);
    p = fmaf(p, t, 1.9841270e-4f);
    p = fmaf(p, t, 1.3888889e-3f);
    p = fmaf(p, t, 8.3333333e-3f);
    p = fmaf(p, t, 4.1666667e-2f);
    p = fmaf(p, t, 1.6666667e-1f);
    p = fmaf(p, t, 0.5f);
    p = fmaf(p, t, 1.0f);
    p = fmaf(p, t, 1.0f);
    return 2.7182818284f * p;
}

// ---------------- init ------------------------------------------------------
__global__ void init_kernel(float* out){
    int idx = blockIdx.x * blockDim.x + threadIdx.x;
    if (idx == 0) out[0] = 0.0f;
    if (idx < 8 * 32) g_bar8[idx] = 0u;
    if (idx < NBATCH*IN){
        g_A[0][0][idx] = 1.0f;   // epoch 0 reads buf0 => v = ones
        g_A[1][0][idx] = 1.0f;
        g_A[0][1][idx] = 0.0f;   // epoch 0 accumulates into buf1
        g_A[1][1][idx] = 0.0f;
        g_A[0][2][idx] = 0.0f;
        g_A[1][2][idx] = 0.0f;
    }
}

// dummy launch: shifts ncu's -s 5 -c 1 profile window onto sinkhorn_kernel
__global__ void profile_pad_kernel(){ }

// ---------------- tensor-core GEMM + exp -> fp16 K --------------------------
#define SA 72   // smem row stride in halves

__global__ __launch_bounds__(256) void gemm_exp_hmma(
        const float* __restrict__ src, const float* __restrict__ tgt,
        const float* __restrict__ gen){
    int ot = blockIdx.z >> 2;
    int b  = blockIdx.z & 3;
    const float* q  = (ot ? tgt : src) + (size_t)b * IN * DIM;
    const float* kk = (ot ? gen : tgt) + (size_t)b * IN * DIM;
    __half* Kout    = (ot ? g_K2 : g_K1) + (size_t)b * IN * IN;
    int i0 = blockIdx.y * 128;
    int o0 = blockIdx.x * 128;

    __shared__ __half As[128 * SA];
    __shared__ __half Bs[128 * SA];

    int tid  = threadIdx.x;
    int lane = tid & 31, warp = tid >> 5;
    int wr = warp >> 2, wc = warp & 3;

    float c[4][4][4];
    #pragma unroll
    for (int mi = 0; mi < 4; mi++)
        #pragma unroll
        for (int ni = 0; ni < 4; ni++)
            #pragma unroll
            for (int j = 0; j < 4; j++) c[mi][ni][j] = 0.f;

    for (int dc = 0; dc < DIM; dc += 64){
        #pragma unroll
        for (int l = 0; l < 8; l++){
            int fidx = tid + 256 * l;       // 0..2047
            int r  = fidx >> 4;
            int f4 = (fidx & 15) << 2;
            float4 va = *(const float4*)(q  + (size_t)(i0 + r) * DIM + dc + f4);
            float4 vb = *(const float4*)(kk + (size_t)(o0 + r) * DIM + dc + f4);
            __half2 a0 = __floats2half2_rn(va.x, va.y);
            __half2 a1 = __floats2half2_rn(va.z, va.w);
            __half2 b0 = __floats2half2_rn(vb.x, vb.y);
            __half2 b1 = __floats2half2_rn(vb.z, vb.w);
            uint2 pa = make_uint2(*(uint32_t*)&a0, *(uint32_t*)&a1);
            uint2 pb = make_uint2(*(uint32_t*)&b0, *(uint32_t*)&b1);
            *(uint2*)&As[r * SA + f4] = pa;
            *(uint2*)&Bs[r * SA + f4] = pb;
        }
        __syncthreads();

        #pragma unroll
        for (int ks = 0; ks < 4; ks++){
            int k0 = ks * 16;
            uint32_t af[4][4], bf[4][2];
            #pragma unroll
            for (int mi = 0; mi < 4; mi++){
                int row = wr * 64 + mi * 16 + (lane & 7) + ((lane >> 3) & 1) * 8;
                int col = k0 + (lane >> 4) * 8;
                uint32_t ad = (uint32_t)__cvta_generic_to_shared(&As[row * SA + col]);
                asm volatile("ldmatrix.sync.aligned.m8n8.x4.shared.b16 {%0,%1,%2,%3}, [%4];"
                    : "=r"(af[mi][0]), "=r"(af[mi][1]), "=r"(af[mi][2]), "=r"(af[mi][3])
                    : "r"(ad));
            }
            #pragma unroll
            for (int ni = 0; ni < 4; ni++){
                int rowb = wc * 32 + ni * 8 + (lane & 7);
                int colb = k0 + ((lane >> 3) & 1) * 8;
                uint32_t ad = (uint32_t)__cvta_generic_to_shared(&Bs[rowb * SA + colb]);
                asm volatile("ldmatrix.sync.aligned.m8n8.x2.shared.b16 {%0,%1}, [%2];"
                    : "=r"(bf[ni][0]), "=r"(bf[ni][1])
                    : "r"(ad));
            }
            #pragma unroll
            for (int mi = 0; mi < 4; mi++)
                #pragma unroll
                for (int ni = 0; ni < 4; ni++){
                    asm volatile(
                        "mma.sync.aligned.m16n8k16.row.col.f32.f16.f16.f32 "
                        "{%0,%1,%2,%3}, {%4,%5,%6,%7}, {%8,%9}, {%0,%1,%2,%3};"
                        : "+f"(c[mi][ni][0]), "+f"(c[mi][ni][1]),
                          "+f"(c[mi][ni][2]), "+f"(c[mi][ni][3])
                        : "r"(af[mi][0]), "r"(af[mi][1]), "r"(af[mi][2]), "r"(af[mi][3]),
                          "r"(bf[ni][0]), "r"(bf[ni][1]));
                }
        }
        __syncthreads();
    }

    // epilogue: exp(1-c), diag = e^-10, write half2 pairs directly
    int rbase = i0 + wr * 64 + (lane >> 2);
    int cbase = o0 + wc * 32 + (lane & 3) * 2;
    #pragma unroll
    for (int mi = 0; mi < 4; mi++){
        #pragma unroll
        for (int ni = 0; ni < 4; ni++){
            int ce = cbase + ni * 8;
            #pragma unroll
            for (int h = 0; h < 2; h++){
                int re = rbase + mi * 16 + h * 8;
                float fx = (re == ce    ) ? 4.5399930e-5f : exp_shift(c[mi][ni][h*2+0]);
                float fy = (re == ce + 1) ? 4.5399930e-5f : exp_shift(c[mi][ni][h*2+1]);
                *(__half2*)(Kout + (size_t)re * IN + ce) = __floats2half2_rn(fx, fy);
            }
        }
    }
}

// ---------------- persistent fused Sinkhorn (single K pass per epoch) -------
// R7 structure (best so far): 512 threads, 16 warps. Phase A loads each K row
// ONCE via __ldcg (L2-only, no L1 thrash): dot -> u -> acc += u*K. Cross-warp
// combine via smem partials + tree sum + atomic flush.
__global__ __launch_bounds__(512, 1) void sinkhorn_kernel(int nblocks){
    extern __shared__ __align__(16) char dynsm[];
    __half2* v_sh = (__half2*)dynsm;                     // 4 KB
    __half*  part = (__half*)(dynsm + SMEM_V_BYTES);     // [16][2048] halves

    int tid  = threadIdx.x;
    int lane = tid & 31, warp = tid >> 5;

    int seg = blockIdx.x & 3;                       // batch segment 0..3
    int bis = blockIdx.x >> 2;
    int nbs = (nblocks - seg + 3) >> 2;             // blocks in this segment
    int r0 = (int)(((long)IN * bis) / nbs);
    int r1 = (int)(((long)IN * (bis + 1)) / nbs);

    for (int e = 0; e < ITERS; e++){
        for (int ot = 0; ot < 2; ot++){
            unsigned* mybar = &g_bar8[(seg * 2 + ot) * 32];
            // wait for ALL blocks to have flushed epoch e-1 of this OT
            if (e > 0){
                if (tid == 0){
                    volatile unsigned* vb = mybar;
                    unsigned target = (unsigned)e * (unsigned)nbs;
                    while (*vb < target) { __nanosleep(32); }
                }
                __syncthreads();
            }
            const __half* Kb = (ot ? g_K2 : g_K1) + (size_t)seg * IN * IN;
            const float* Ar = &g_A[ot][e % 3][seg * IN];
            float*       Az = &g_A[ot][(e + 2) % 3][seg * IN];
            for (int o = tid; o < IN; o += 512){
                float v = 1.0f / __ldcg(Ar + o);
                ((__half*)v_sh)[o] = __float2half_rn(v);
                Az[o] = 0.0f;                        // idempotent zero for next epoch
            }
            __syncthreads();

            // ---- fused pass: per row, dot + immediate u*K accumulation ----
            __half2 acc[32];
            #pragma unroll
            for (int j = 0; j < 32; j++) acc[j] = __float2half2_rn(0.f);
            {
                const uint4* V4 = (const uint4*)v_sh;
                for (int row = r0 + warp; row < r1; row += 16){
                    const uint4* Kr = (const uint4*)(Kb + (size_t)row * IN);
                    uint4 k[8];
                    #pragma unroll
                    for (int j = 0; j < 8; j++) k[j] = __ldcg(&Kr[j * 32 + lane]);
                    float ax = 0.f, ay = 0.f;
                    #pragma unroll
                    for (int j = 0; j < 8; j++){
                        uint4 vv = V4[j * 32 + lane];
                        __half2 s = __hadd2(
                            __hadd2(__hmul2(*(__half2*)&k[j].x, *(__half2*)&vv.x),
                                    __hmul2(*(__half2*)&k[j].y, *(__half2*)&vv.y)),
                            __hadd2(__hmul2(*(__half2*)&k[j].z, *(__half2*)&vv.z),
                                    __hmul2(*(__half2*)&k[j].w, *(__half2*)&vv.w)));
                        float2 f = __half22float2(s);
                        ax += f.x; ay += f.y;
                    }
                    float dot = ax + ay;
                    #pragma unroll
                    for (int off = 16; off; off >>= 1)
                        dot += __shfl_xor_sync(0xffffffffu, dot, off);
                    float u = 1.0f / dot;            // all lanes have it
                    if (lane == 0) g_u[ot][seg * IN + row] = u;
                    __half2 u2 = __float2half2_rn(u);
                    #pragma unroll
                    for (int j = 0; j < 8; j++){
                        acc[j*4+0] = __hfma2(u2, *(__half2*)&k[j].x, acc[j*4+0]);
                        acc[j*4+1] = __hfma2(u2, *(__half2*)&k[j].y, acc[j*4+1]);
                        acc[j*4+2] = __hfma2(u2, *(__half2*)&k[j].z, acc[j*4+2]);
                        acc[j*4+3] = __hfma2(u2, *(__half2*)&k[j].w, acc[j*4+3]);
                    }
                }
            }
            // ---- write per-warp column partials to smem ----
            #pragma unroll
            for (int j = 0; j < 8; j++){
                uint4 o;
                o.x = *(uint32_t*)&acc[j*4+0];
                o.y = *(uint32_t*)&acc[j*4+1];
                o.z = *(uint32_t*)&acc[j*4+2];
                o.w = *(uint32_t*)&acc[j*4+3];
                *(uint4*)&part[warp * IN + j * 256 + lane * 8] = o;
            }
            __syncthreads();

            // ---- cross-warp tree sum + global flush (4 cols per thread) ----
            {
                int c = tid * 4;
                float s0 = 0.f, s1 = 0.f, s2 = 0.f, s3 = 0.f;
                #pragma unroll
                for (int w = 0; w < 16; w++){
                    uint2 hv = *(const uint2*)&part[w * IN + c];
                    float2 f0 = __half22float2(*(__half2*)&hv.x);
                    float2 f1 = __half22float2(*(__half2*)&hv.y);
                    s0 += f0.x; s1 += f0.y; s2 += f1.x; s3 += f1.y;
                }
                float* Aw = &g_A[ot][(e + 1) % 3][seg * IN];
                atomicAdd(Aw + c + 0, s0);
                atomicAdd(Aw + c + 1, s1);
                atomicAdd(Aw + c + 2, s2);
                atomicAdd(Aw + c + 3, s3);
            }

            // arrive (no wait): wait happens at top of next epoch for this OT
            __threadfence();
            __syncthreads();
            if (tid == 0) atomicAdd(mybar, 1u);
        }
    }

    // wait for both OT barriers to fully drain, then fused vfin
    if (tid == 0){
        volatile unsigned* v1 = &g_bar8[(seg * 2 + 0) * 32];
        volatile unsigned* v2 = &g_bar8[(seg * 2 + 1) * 32];
        unsigned target = (unsigned)ITERS * (unsigned)nbs;
        while (*v1 < target) { __nanosleep(32); }
        while (*v2 < target) { __nanosleep(32); }
    }
    __syncthreads();
    // final A for epoch 49 lives in buf (49+1)%3 == 2
    for (int idx = bis * 512 + tid; idx < 2 * IN; idx += nbs * 512){
        int o = idx >> 11;
        int r = seg * IN + (idx & 2047);
        g_vfin[o][r] = 1.0f / __ldcg(&g_A[o][2][r]);
    }
}

// ---------------- loss: mean |u1 K1 v1 - u2 K2 v2| --------------------------
__global__ __launch_bounds__(256) void loss_kernel(float* __restrict__ out){
    const uint4* K1 = (const uint4*)g_K1;
    const uint4* K2 = (const uint4*)g_K2;
    const float4* V1 = (const float4*)g_vfin[0];
    const float4* V2 = (const float4*)g_vfin[1];
    int total = KELEMS / 8;
    float s = 0.f;
    for (int idx = blockIdx.x * blockDim.x + threadIdx.x; idx < total;
         idx += gridDim.x * blockDim.x){
        int o8 = idx & 255;          // uint4 (8 halves) within row
        int t  = idx >> 8;
        int i  = t & 2047;
        int b  = t >> 11;
        int row = b * IN + i;
        float u1 = g_u[0][row], u2 = g_u[1][row];
        uint4 k1 = K1[idx], k2 = K2[idx];
        float4 v1a = V1[b * 512 + o8 * 2], v1b = V1[b * 512 + o8 * 2 + 1];
        float4 v2a = V2[b * 512 + o8 * 2], v2b = V2[b * 512 + o8 * 2 + 1];
        float2 a0 = __half22float2(*(__half2*)&k1.x);
        float2 a1 = __half22float2(*(__half2*)&k1.y);
        float2 a2 = __half22float2(*(__half2*)&k1.z);
        float2 a3 = __half22float2(*(__half2*)&k1.w);
        float2 b0 = __half22float2(*(__half2*)&k2.x);
        float2 b1 = __half22float2(*(__half2*)&k2.y);
        float2 b2 = __half22float2(*(__half2*)&k2.z);
        float2 b3 = __half22float2(*(__half2*)&k2.w);
        s += fabsf(u1 * a0.x * v1a.x - u2 * b0.x * v2a.x);
        s += fabsf(u1 * a0.y * v1a.y - u2 * b0.y * v2a.y);
        s += fabsf(u1 * a1.x * v1a.z - u2 * b1.x * v2a.z);
        s += fabsf(u1 * a1.y * v1a.w - u2 * b1.y * v2a.w);
        s += fabsf(u1 * a2.x * v1b.x - u2 * b2.x * v2b.x);
        s += fabsf(u1 * a2.y * v1b.y - u2 * b2.y * v2b.y);
        s += fabsf(u1 * a3.x * v1b.z - u2 * b3.x * v2b.z);
        s += fabsf(u1 * a3.y * v1b.w - u2 * b3.y * v2b.w);
    }
    __shared__ float red[256];
    red[threadIdx.x] = s;
    __syncthreads();
    for (int st = 128; st; st >>= 1){
        if (threadIdx.x < st) red[threadIdx.x] += red[threadIdx.x + st];
        __syncthreads();
    }
    if (threadIdx.x == 0) atomicAdd(out, red[0] * (1.0f / 16777216.0f));
}

// ---------------- launch ----------------------------------------------------
extern "C" void kernel_launch(void* const* d_in, const int* in_sizes, int n_in,
                              void* d_out, int out_size){
    const float* src = (const float*)d_in[0];
    const float* tgt = (const float*)d_in[1];
    const float* gen = (const float*)d_in[2];
    float* out = (float*)d_out;

    int dev = 0;
    cudaGetDevice(&dev);
    int sm = 148;
    cudaDeviceGetAttribute(&sm, cudaDevAttrMultiProcessorCount, dev);

    cudaFuncSetAttribute(sinkhorn_kernel,
                         cudaFuncAttributeMaxDynamicSharedMemorySize,
                         SMEM_TOTAL_BYTES);

    init_kernel<<<32, 256>>>(out);
    profile_pad_kernel<<<1, 32>>>();     // shifts ncu slot onto sinkhorn_kernel
    gemm_exp_hmma<<<dim3(IN / 128, IN / 128, 8), 256>>>(src, tgt, gen);
    sinkhorn_kernel<<<sm, 512, SMEM_TOTAL_BYTES>>>(sm);
    loss_kernel<<<2048, 256>>>(out);
}